// round 6
// baseline (speedup 1.0000x reference)
#include <cuda_runtime.h>
#include <stdint.h>

// Problem constants (fixed by setup_inputs): B=32, T=512, dur < 16.
#define B_SZ 32
#define T_SZ 512
#define M_MAX (T_SZ * 15)   // worst-case frames per row = 7680

// frame -> token map, -1 for padding frames. Scratch as __device__ global.
__device__ int g_f2t[B_SZ * M_MAX];

// Kernel A: one block per batch row. Warp-shuffle inclusive scan of the 512
// durations, then each token scatters its index over its frame range.
__global__ void __launch_bounds__(T_SZ) build_f2t_kernel(
    const int* __restrict__ dur, int M)
{
    __shared__ int warp_sum[16];
    const int b    = blockIdx.x;
    const int t    = threadIdx.x;
    const int lane = t & 31;
    const int wid  = t >> 5;

    const int d = dur[b * T_SZ + t];

    int v = d;
    #pragma unroll
    for (int off = 1; off < 32; off <<= 1) {
        int u = __shfl_up_sync(0xFFFFFFFF, v, off);
        if (lane >= off) v += u;
    }
    if (lane == 31) warp_sum[wid] = v;
    __syncthreads();

    if (wid == 0 && lane < 16) {
        int s = warp_sum[lane];
        #pragma unroll
        for (int off = 1; off < 16; off <<= 1) {
            int u = __shfl_up_sync(0xFFFF, s, off);
            if (lane >= off) s += u;
        }
        warp_sum[lane] = s - warp_sum[lane];   // exclusive
    }
    __syncthreads();

    const int end   = v + warp_sum[wid];
    const int start = end - d;

    int* row = g_f2t + b * M;
    for (int f = t; f < M; f += T_SZ) row[f] = -1;
    __syncthreads();

    for (int f = start; f < end; f++) row[f] = t;
}

// Kernel B v4: per-thread independent chains (the v2 structure that won),
// widened to 8 float4 per thread, all-32-bit indexing. Block of 256 threads
// covers a contiguous 2048-float4 (32 KB) chunk; thread's k-th element at
// +k*256 keeps every STG.128 perfectly coalesced. toks gathered up front ->
// 8 outstanding LDGs (MLP=8) before any dependent store.
// n4 = 4096*M is always a multiple of 2048.
__global__ void __launch_bounds__(256) write_align_kernel8(
    float4* __restrict__ out)
{
    const unsigned base = blockIdx.x * 2048u + threadIdx.x;

    int toks[8];
    #pragma unroll
    for (int k = 0; k < 8; k++) {
        const unsigned idx = base + k * 256u;
        toks[k] = __ldg(&g_f2t[idx >> 7]);       // (b,f) row; T/4 = 128
    }

    #pragma unroll
    for (int k = 0; k < 8; k++) {
        const unsigned idx = base + k * 256u;
        const int tok = toks[k];
        const int t0  = ((int)idx & 127) << 2;   // first token column
        float4 v;
        v.x = (t0     == tok) ? 1.0f : 0.0f;
        v.y = (t0 + 1 == tok) ? 1.0f : 0.0f;
        v.z = (t0 + 2 == tok) ? 1.0f : 0.0f;
        v.w = (t0 + 3 == tok) ? 1.0f : 0.0f;
        __stcs(&out[idx], v);
    }
}

// Fallback (guarded, 1 float4/thread) for any shape where n4 % 2048 != 0.
__global__ void __launch_bounds__(256) write_align_kernel1(
    float4* __restrict__ out, long long n4)
{
    const long long idx = (long long)blockIdx.x * blockDim.x + threadIdx.x;
    if (idx >= n4) return;
    const long long row = idx >> 7;
    const int tok = __ldg(&g_f2t[row]);
    const int t0  = ((int)idx & 127) << 2;
    float4 v;
    v.x = (t0     == tok) ? 1.0f : 0.0f;
    v.y = (t0 + 1 == tok) ? 1.0f : 0.0f;
    v.z = (t0 + 2 == tok) ? 1.0f : 0.0f;
    v.w = (t0 + 3 == tok) ? 1.0f : 0.0f;
    __stcs(&out[idx], v);
}

extern "C" void kernel_launch(void* const* d_in, const int* in_sizes, int n_in,
                              void* d_out, int out_size)
{
    const int* dur = (const int*)d_in[0];

    // out is [B, M, T] float32; derive M from out_size.
    const int M = out_size / (B_SZ * T_SZ);

    build_f2t_kernel<<<B_SZ, T_SZ>>>(dur, M);

    const long long n4 = (long long)out_size / 4;
    if ((n4 & 2047) == 0) {
        write_align_kernel8<<<(unsigned)(n4 >> 11), 256>>>((float4*)d_out);
    } else {
        const long long blocks = (n4 + 255) / 256;
        write_align_kernel1<<<(unsigned)blocks, 256>>>((float4*)d_out, n4);
    }
}